// round 10
// baseline (speedup 1.0000x reference)
#include <cuda_runtime.h>
#include <cstdint>

// Problem constants
#define MAX_DIST 35.0f
#define BOX 71            // ceil(2*35/1 + 1)
#define FDIM 32
#define BATCH 8
#define NPTS 16384

// Derived sizes (in float4 units)
#define SLICE0_F4 (BOX * BOX * BOX * FDIM / 4)          // 2,863,288
#define TOTAL_F4  (BATCH * BOX * BOX * BOX * FDIM / 4)  // 22,906,304
#define SCATTER_WORK (BATCH * NPTS * (FDIM / 4))        // 1,048,576 point-quads
#define NTHREADS SCATTER_WORK                           // 1 scatter item / thread

#define A_BLOCKS (148 * 8)                              // one full wave
#define A_THREADS (A_BLOCKS * 256)

// ---------------------------------------------------------------------------
// Kernel A: zero batch slice 0 (45.8 MB) with PLAIN stores -> L2-resident
// (write-allocate; 45.8 MB << 126 MB L2). Kernel B's atomics fire shortly
// after the PDL sync, while slice 0 is still in L2 -> atomic RMW becomes an
// L2 hit (saves the ~13 MB DRAM read-back R8/R9 paid). The single obligatory
// 45.8 MB writeback drains lazily under B's 320 MB store phase.
// ---------------------------------------------------------------------------
__global__ void __launch_bounds__(256)
zero_slice0_kernel(float4* __restrict__ out) {
    const float4 z = make_float4(0.f, 0.f, 0.f, 0.f);
    for (int i = blockIdx.x * blockDim.x + threadIdx.x; i < SLICE0_F4;
         i += A_THREADS) {
        out[i] = z;                    // plain store: L2 write-allocate
    }
}

// ---------------------------------------------------------------------------
// Kernel B (fused, PDL early-launch): 1,048,576 threads (4096 x 256).
//   Per thread:
//     1. issue scatter input loads (coords + feature quad),
//     2. 3 pre-sync zero batches into slices 1..7 (48 MB grid-wide: covers
//        A's runtime under PDL, hides load latency, but does NOT thrash
//        slice 0 out of L2 before the atomics fire),
//     3. cudaGridDependencySynchronize()  -- wait for A's zeros (L2-visible),
//     4. fire one red.global.add.v4.f32 into batch slice 0 (L2 hit),
//     5. stream the remaining ~17 zero batches (__stcs evict-first).
// Scatter semantics (faithful to the reference):
//   - ALL B*N points land in batch slice 0 (reference's tf.zeros batch column)
//   - round-half-to-even via __float2int_rn (jnp.round)
//   - out-of-box points contribute exactly +0.0 -> skipped
// ---------------------------------------------------------------------------
__global__ void __launch_bounds__(256)
fused_scatter_zero_kernel(const float* __restrict__ coords,
                          const float4* __restrict__ features4,
                          float* __restrict__ out) {
    const int tid = blockIdx.x * blockDim.x + threadIdx.x;

    const int p = tid >> 3;        // global point index (b*N + n)
    const int q = tid & 7;         // which float4 of the 8 covering F=32

    // Scatter inputs issued up front; latency hides under the stores below.
    float c0 = __ldg(&coords[p * 3 + 0]);
    float c1 = __ldg(&coords[p * 3 + 1]);
    float c2 = __ldg(&coords[p * 3 + 2]);
    float4 v = __ldg(&features4[(long long)p * 8 + q]);

    float4* out4 = (float4*)out;
    const float4 z = make_float4(0.f, 0.f, 0.f, 0.f);

    long long i = (long long)SLICE0_F4 + tid;

    // Pre-sync work (concurrent with kernel A under PDL): 3 batches = 48 MB.
    #pragma unroll
    for (int k = 0; k < 3; k++) {
        if (i < TOTAL_F4) { __stcs(&out4[i], z); }
        i += NTHREADS;
    }

    // Wait for kernel A's slice-0 zeros (PDL; stores visible at L2).
    cudaGridDependencySynchronize();

    // Scatter EARLY, while slice 0 is still L2-resident.
    {
        int g0 = __float2int_rn(c0 + MAX_DIST);
        int g1 = __float2int_rn(c1 + MAX_DIST);
        int g2 = __float2int_rn(c2 + MAX_DIST);
        if ((unsigned)g0 < BOX && (unsigned)g1 < BOX && (unsigned)g2 < BOX) {
            int cell = (g0 * BOX + g1) * BOX + g2;
            float* dst = out + (long long)cell * FDIM + q * 4;  // slice 0
            asm volatile("red.global.add.v4.f32 [%0], {%1, %2, %3, %4};"
                         :: "l"(dst), "f"(v.x), "f"(v.y), "f"(v.z), "f"(v.w)
                         : "memory");
        }
    }

    // Remaining zero stores (evict-first streaming).
    for (; i < TOTAL_F4; i += NTHREADS) {
        __stcs(&out4[i], z);
    }
}

extern "C" void kernel_launch(void* const* d_in, const int* in_sizes, int n_in,
                              void* d_out, int out_size) {
    const float* coords = (const float*)d_in[0];     // [8,16384,3] f32
    const float4* feats = (const float4*)d_in[1];    // [8,16384,32] f32 as float4
    float* out = (float*)d_out;                      // [8,71,71,71,32] f32

    // Kernel A: zero slice 0 into L2 (plain stores).
    zero_slice0_kernel<<<A_BLOCKS, 256>>>((float4*)out);

    // Kernel B: PDL early launch — overlaps A, atomics fire right after sync.
    cudaLaunchConfig_t cfg = {};
    cfg.gridDim = dim3(SCATTER_WORK / 256, 1, 1);
    cfg.blockDim = dim3(256, 1, 1);
    cfg.dynamicSmemBytes = 0;
    cudaLaunchAttribute attr[1];
    attr[0].id = cudaLaunchAttributeProgrammaticStreamSerialization;
    attr[0].val.programmaticStreamSerializationAllowed = 1;
    cfg.attrs = attr;
    cfg.numAttrs = 1;
    cudaLaunchKernelEx(&cfg, fused_scatter_zero_kernel, coords, feats, out);
}

// round 11
// speedup vs baseline: 1.0764x; 1.0764x over previous
#include <cuda_runtime.h>
#include <cstdint>

// Problem constants
#define MAX_DIST 35.0f
#define BOX 71            // ceil(2*35/1 + 1)
#define FDIM 32
#define BATCH 8
#define NPTS 16384

#define NPOINTS (BATCH * NPTS)               // 131,072
#define NCELLS  (BOX * BOX * BOX)            // 357,911
#define SLICE0_F4 (NCELLS * (FDIM / 4))      // 2,863,288 float4 = slice 0
#define TOTAL_F4  (SLICE0_F4 * BATCH)        // 22,906,304

// Per-cell linked lists (scratch; __device__ globals are legal).
// head must be re-initialized every replay; next[i] is always written in K1
// before K2 reads it (only list members are ever read).
__device__ int d_head[NCELLS];               // 1.4 MB
__device__ int d_next[NPOINTS];              // 0.5 MB

// ---------------------------------------------------------------------------
// K0: reset list heads. Tiny (1.4 MB of stores).
// ---------------------------------------------------------------------------
__global__ void __launch_bounds__(256)
init_heads_kernel() {
    int i = blockIdx.x * blockDim.x + threadIdx.x;
    if (i < NCELLS) d_head[i] = -1;
}

// ---------------------------------------------------------------------------
// K1: build per-cell lists. cell = round-half-to-even((c+35)/1) per axis
// (faithful to jnp.round); out-of-box points are excluded (they contribute
// exactly +0.0 in the reference). All B*N points map into batch slice 0
// (reference's tf.zeros batch column). PDL-synced on K0.
// ---------------------------------------------------------------------------
__global__ void __launch_bounds__(256)
build_lists_kernel(const float* __restrict__ coords) {
    int i = blockIdx.x * blockDim.x + threadIdx.x;    // 0 .. NPOINTS-1
    float c0 = __ldg(&coords[i * 3 + 0]);
    float c1 = __ldg(&coords[i * 3 + 1]);
    float c2 = __ldg(&coords[i * 3 + 2]);
    int g0 = __float2int_rn(c0 + MAX_DIST);
    int g1 = __float2int_rn(c1 + MAX_DIST);
    int g2 = __float2int_rn(c2 + MAX_DIST);

    cudaGridDependencySynchronize();   // K0's head init must be visible
    if ((unsigned)g0 < BOX && (unsigned)g1 < BOX && (unsigned)g2 < BOX) {
        int cell = (g0 * BOX + g1) * BOX + g2;
        d_next[i] = atomicExch(&d_head[cell], i);
    }
}

// ---------------------------------------------------------------------------
// K2: gather + zero. One thread per (cell, quad): tid in [0, SLICE0_F4).
//   1. stream 7 zeros into slices 1..7 (independent of K1 -> pre-sync,
//      overlaps K0/K1 under PDL),
//   2. PDL sync on K1,
//   3. walk the cell's point list, accumulating feats[pid*8+q]
//      (8 quad-threads of a cell are consecutive -> 128B-coalesced reads,
//       head/next are L2-resident broadcasts),
//   4. stream the accumulated float4 as the slice-0 value.
// Every output byte is written exactly once; no atomics on the output.
// ---------------------------------------------------------------------------
__global__ void __launch_bounds__(256)
gather_zero_kernel(const float4* __restrict__ feats,
                   float* __restrict__ out) {
    const int tid = blockIdx.x * blockDim.x + threadIdx.x;
    if (tid >= SLICE0_F4) return;                  // 72 pad threads

    float4* out4 = (float4*)out;
    const float4 z = make_float4(0.f, 0.f, 0.f, 0.f);

    // Zero slices 1..7: 7 stores, each a fully coalesced stream per slice.
    #pragma unroll
    for (int k = 1; k < BATCH; k++) {
        __stcs(&out4[(long long)k * SLICE0_F4 + tid], z);
    }

    cudaGridDependencySynchronize();               // wait for K1's lists

    const int cell = tid >> 3;
    const int q = tid & 7;

    int pid = d_head[cell];
    float4 acc = z;
    while (pid >= 0) {
        float4 v = __ldg(&feats[(long long)pid * 8 + q]);
        acc.x += v.x; acc.y += v.y; acc.z += v.z; acc.w += v.w;
        pid = d_next[pid];
    }
    __stcs(&out4[tid], acc);                       // slice 0, written once
}

extern "C" void kernel_launch(void* const* d_in, const int* in_sizes, int n_in,
                              void* d_out, int out_size) {
    const float* coords = (const float*)d_in[0];     // [8,16384,3] f32
    const float4* feats = (const float4*)d_in[1];    // [8,16384,32] f32 as float4
    float* out = (float*)d_out;                      // [8,71,71,71,32] f32

    cudaLaunchAttribute pdl[1];
    pdl[0].id = cudaLaunchAttributeProgrammaticStreamSerialization;
    pdl[0].val.programmaticStreamSerializationAllowed = 1;

    // K0: reset heads (plain launch).
    init_heads_kernel<<<(NCELLS + 255) / 256, 256>>>();

    // K1: build lists — PDL early launch over K0.
    {
        cudaLaunchConfig_t cfg = {};
        cfg.gridDim = dim3(NPOINTS / 256, 1, 1);     // 512 blocks
        cfg.blockDim = dim3(256, 1, 1);
        cfg.attrs = pdl; cfg.numAttrs = 1;
        cudaLaunchKernelEx(&cfg, build_lists_kernel, coords);
    }

    // K2: gather + zero — PDL early launch over K1 (its slice-1..7 stores
    // run concurrently with K0/K1; only the list walk waits).
    {
        cudaLaunchConfig_t cfg = {};
        cfg.gridDim = dim3((SLICE0_F4 + 255) / 256, 1, 1);  // 11185 blocks
        cfg.blockDim = dim3(256, 1, 1);
        cfg.attrs = pdl; cfg.numAttrs = 1;
        cudaLaunchKernelEx(&cfg, gather_zero_kernel, feats, out);
    }
}